// round 6
// baseline (speedup 1.0000x reference)
#include <cuda_runtime.h>
#include <cstdint>
#include <cstddef>

#define TT 256
#define BB 64
#define DD 512
#define HH 1024
#define GG 4096
#define EPSB 1e-5f

// ---------------- scratch (device globals: no allocation allowed) ----------------
__device__ float g_xw[(size_t)TT * BB * GG];   // 256 MB: raw x@w_ih (BN applied in step kernel)
__device__ float g_y0[(size_t)TT * BB * HH];   // 64 MB: layer-0 output
__device__ float g_h[2][BB * HH];              // ping-pong hidden state
__device__ float g_c[BB * HH];                 // cell state (in-place)
__device__ float g_wpack[HH * GG];             // per-block packed recurrent weights

// ---------------- packed f32x2 + fast-math helpers ----------------
__device__ __forceinline__ void fma2(unsigned long long& d, unsigned long long a, unsigned long long b) {
    asm("fma.rn.f32x2 %0, %1, %2, %3;" : "=l"(d) : "l"(a), "l"(b), "l"(d));
}
__device__ __forceinline__ float2 upk2(unsigned long long v) {
    float lo, hi;
    asm("mov.b64 {%0, %1}, %2;" : "=f"(lo), "=f"(hi) : "l"(v));
    return make_float2(lo, hi);
}
__device__ __forceinline__ float tanh_f(float x) {
    float r;
    asm("tanh.approx.f32 %0, %1;" : "=f"(r) : "f"(x));
    return r;
}
__device__ __forceinline__ float sigf(float x) { return fmaf(tanh_f(0.5f * x), 0.5f, 0.5f); }

// ---------------- input GEMM: g_xw(raw) = A(16384 x K) @ W(K x 4096) ----------------
// 64x64 tile, 256 threads, thread tile 4b x 4c. Weights duplicated in smem so the
// inner step is 3x LDS.128 + 8x FFMA2 (fma-throughput bound).
__global__ __launch_bounds__(256) void gemm_xw_kernel(const float* __restrict__ A,
                                                      const float* __restrict__ W, int K) {
    __shared__ __align__(16) float As[2][16][68];    // [k][m] transposed
    __shared__ __align__(16) float Bd[2][16][132];   // [k][2*n] duplicated pairs
    const int n0 = blockIdx.x * 64, m0 = blockIdx.y * 64;
    const int tid = threadIdx.x;
    const int mt = tid & 15, nt = tid >> 4;
    const int r0 = mt * 4, c0 = nt * 4;
    const int lm = tid >> 2, lk = (tid & 3) * 4;   // A loader
    const int bk = tid >> 4, bn = (tid & 15) * 4;  // B loader
    const float* pA = A + (size_t)(m0 + lm) * K + lk;
    const float* pB = W + (size_t)bk * GG + n0 + bn;

    unsigned long long acc[2][4] = {};

    float4 va = *(const float4*)pA;
    float4 vb = *(const float4*)pB;
    As[0][lk + 0][lm] = va.x; As[0][lk + 1][lm] = va.y;
    As[0][lk + 2][lm] = va.z; As[0][lk + 3][lm] = va.w;
    *(float2*)&Bd[0][bk][2 * (bn + 0)] = make_float2(vb.x, vb.x);
    *(float2*)&Bd[0][bk][2 * (bn + 1)] = make_float2(vb.y, vb.y);
    *(float2*)&Bd[0][bk][2 * (bn + 2)] = make_float2(vb.z, vb.z);
    *(float2*)&Bd[0][bk][2 * (bn + 3)] = make_float2(vb.w, vb.w);
    __syncthreads();

    int buf = 0;
    for (int k0 = 16; k0 <= K; k0 += 16) {
        const bool more = (k0 < K);
        if (more) {
            va = *(const float4*)(pA + k0);
            vb = *(const float4*)(pB + (size_t)k0 * GG);
        }
#pragma unroll
        for (int k = 0; k < 16; k++) {
            ulonglong2 av  = *(const ulonglong2*)&As[buf][k][r0];
            ulonglong2 w01 = *(const ulonglong2*)&Bd[buf][k][2 * c0];
            ulonglong2 w23 = *(const ulonglong2*)&Bd[buf][k][2 * c0 + 4];
            fma2(acc[0][0], av.x, w01.x); fma2(acc[1][0], av.y, w01.x);
            fma2(acc[0][1], av.x, w01.y); fma2(acc[1][1], av.y, w01.y);
            fma2(acc[0][2], av.x, w23.x); fma2(acc[1][2], av.y, w23.x);
            fma2(acc[0][3], av.x, w23.y); fma2(acc[1][3], av.y, w23.y);
        }
        if (more) {
            int nb = buf ^ 1;
            As[nb][lk + 0][lm] = va.x; As[nb][lk + 1][lm] = va.y;
            As[nb][lk + 2][lm] = va.z; As[nb][lk + 3][lm] = va.w;
            *(float2*)&Bd[nb][bk][2 * (bn + 0)] = make_float2(vb.x, vb.x);
            *(float2*)&Bd[nb][bk][2 * (bn + 1)] = make_float2(vb.y, vb.y);
            *(float2*)&Bd[nb][bk][2 * (bn + 2)] = make_float2(vb.z, vb.z);
            *(float2*)&Bd[nb][bk][2 * (bn + 3)] = make_float2(vb.w, vb.w);
            __syncthreads();
            buf = nb;
        }
    }
#pragma unroll
    for (int rp = 0; rp < 2; rp++) {
        float2 u0 = upk2(acc[rp][0]), u1 = upk2(acc[rp][1]),
               u2 = upk2(acc[rp][2]), u3 = upk2(acc[rp][3]);
        *(float4*)&g_xw[(size_t)(m0 + r0 + 2 * rp) * GG + n0 + c0] =
            make_float4(u0.x, u1.x, u2.x, u3.x);
        *(float4*)&g_xw[(size_t)(m0 + r0 + 2 * rp + 1) * GG + n0 + c0] =
            make_float4(u0.y, u1.y, u2.y, u3.y);
    }
}

// ---------------- pack w_hh so block blk owns gate cols {g*H + blk*4 + j : g<4, j<4} ----------------
__global__ void pack_w_kernel(const float* __restrict__ w) {
    const int idx = blockIdx.x * 256 + threadIdx.x;  // < HH*GG
    const int c = idx & 15;
    const int k = (idx >> 4) & (HH - 1);
    const int blk = idx >> 14;
    g_wpack[idx] = w[(size_t)k * GG + (c >> 2) * HH + blk * 4 + (c & 3)];
}

__global__ void init_hc_kernel() {
    const int i = blockIdx.x * 256 + threadIdx.x;
    if (i < BB * HH) { g_h[0][i] = 0.f; g_h[1][i] = 0.f; g_c[i] = 0.f; }
}

__global__ void copy_hc_kernel(float* __restrict__ oh, float* __restrict__ oc) {
    const int i = blockIdx.x * 256 + threadIdx.x;
    if (i < BB * HH) { oh[i] = g_h[0][i]; oc[i] = g_c[i]; }
}

// ---------------- one LSTM timestep ----------------
// 256 blocks; block blk owns h-cols [blk*4, blk*4+4) and the 16 gate cols
// {g*1024 + blk*4 + j}. Both BN-ih and BN-hh stats are block-local.
__global__ __launch_bounds__(128) void lstm_step_kernel(
    int t, int par,
    const float* __restrict__ ghh, const float* __restrict__ bthh,
    const float* __restrict__ gih, const float* __restrict__ btih,
    const float* __restrict__ bias,
    const float* __restrict__ gcb, const float* __restrict__ btcb,
    const int* __restrict__ length, float* __restrict__ y_out) {
    __shared__ __align__(16) float hsT[2][32][68];   // [k][b] transposed
    __shared__ __align__(16) float wdup[2][32][36];  // [k][2*c] duplicated pairs
    __shared__ __align__(16) float Cs[64][20];       // h@w_hh result (b, local c)
    __shared__ __align__(16) float Xs[64][20];       // raw x@w_ih slice
    __shared__ float redA[8][16], redB[8][16], redC[8][16], redD[8][16];
    __shared__ float scH[16], shH[16], scX[16], shX[16];
    __shared__ float c1s[64][5], oss[64][5];
    __shared__ float scc[4], shc[4];

    const int blk = blockIdx.x, tid = threadIdx.x;
    const float* hin = g_h[par];
    float* hout = g_h[par ^ 1];
    const float* wp = g_wpack + (size_t)blk * 16384;

    // ---- early gmem loads (latency hidden under the GEMM) ----
    float4 xwv[2]; float coldr[2]; int lenr[2];
#pragma unroll
    for (int i = 0; i < 2; i++) {
        int idx = tid + i * 128;
        int b = idx >> 2, g = idx & 3;
        xwv[i] = *(const float4*)&g_xw[((size_t)t * BB + b) * GG + g * HH + blk * 4];
        int j = g;  // same bit-field, used as j for c/length
        coldr[i] = g_c[b * HH + blk * 4 + j];
        lenr[i] = length[b];
    }

    // ---- GEMM: Cs(64x16) = hin(64x1024) @ wp(1024x16) ----
    const int rt = tid >> 3, ct = tid & 7;   // warp shares av 4-ways, wv 8-ways
    const int r0 = rt * 4, c0 = ct * 2;
    unsigned long long acc[2][2] = {};

    float4 ph[4], pw;
    const int wkk = tid >> 2, wc4 = (tid & 3) * 4;
#pragma unroll
    for (int i = 0; i < 4; i++) {
        int idx = tid + i * 128;
        ph[i] = *(const float4*)&hin[(idx >> 3) * HH + (idx & 7) * 4];
    }
    pw = *(const float4*)&wp[wkk * 16 + wc4];
#pragma unroll
    for (int i = 0; i < 4; i++) {
        int idx = tid + i * 128;
        int b = idx >> 3, kq = (idx & 7) * 4;
        hsT[0][kq + 0][b] = ph[i].x; hsT[0][kq + 1][b] = ph[i].y;
        hsT[0][kq + 2][b] = ph[i].z; hsT[0][kq + 3][b] = ph[i].w;
    }
    *(float2*)&wdup[0][wkk][2 * (wc4 + 0)] = make_float2(pw.x, pw.x);
    *(float2*)&wdup[0][wkk][2 * (wc4 + 1)] = make_float2(pw.y, pw.y);
    *(float2*)&wdup[0][wkk][2 * (wc4 + 2)] = make_float2(pw.z, pw.z);
    *(float2*)&wdup[0][wkk][2 * (wc4 + 3)] = make_float2(pw.w, pw.w);
    __syncthreads();

    int buf = 0;
    for (int kc = 32; kc <= HH; kc += 32) {
        const bool more = (kc < HH);
        if (more) {
#pragma unroll
            for (int i = 0; i < 4; i++) {
                int idx = tid + i * 128;
                ph[i] = *(const float4*)&hin[(idx >> 3) * HH + kc + (idx & 7) * 4];
            }
            pw = *(const float4*)&wp[(kc + wkk) * 16 + wc4];
        }
#pragma unroll
        for (int k = 0; k < 32; k++) {
            ulonglong2 av = *(const ulonglong2*)&hsT[buf][k][r0];
            ulonglong2 wv = *(const ulonglong2*)&wdup[buf][k][4 * ct];
            fma2(acc[0][0], av.x, wv.x); fma2(acc[1][0], av.y, wv.x);
            fma2(acc[0][1], av.x, wv.y); fma2(acc[1][1], av.y, wv.y);
        }
        if (more) {
            int nb = buf ^ 1;
#pragma unroll
            for (int i = 0; i < 4; i++) {
                int idx = tid + i * 128;
                int b = idx >> 3, kq = (idx & 7) * 4;
                hsT[nb][kq + 0][b] = ph[i].x; hsT[nb][kq + 1][b] = ph[i].y;
                hsT[nb][kq + 2][b] = ph[i].z; hsT[nb][kq + 3][b] = ph[i].w;
            }
            *(float2*)&wdup[nb][wkk][2 * (wc4 + 0)] = make_float2(pw.x, pw.x);
            *(float2*)&wdup[nb][wkk][2 * (wc4 + 1)] = make_float2(pw.y, pw.y);
            *(float2*)&wdup[nb][wkk][2 * (wc4 + 2)] = make_float2(pw.z, pw.z);
            *(float2*)&wdup[nb][wkk][2 * (wc4 + 3)] = make_float2(pw.w, pw.w);
            __syncthreads();
            buf = nb;
        }
    }

    // ---- stage GEMM result + xw slice in smem ----
#pragma unroll
    for (int p = 0; p < 2; p++) {
        float2 u0 = upk2(acc[p][0]), u1 = upk2(acc[p][1]);
        *(float2*)&Cs[r0 + 2 * p][c0]     = make_float2(u0.x, u1.x);
        *(float2*)&Cs[r0 + 2 * p + 1][c0] = make_float2(u0.y, u1.y);
    }
#pragma unroll
    for (int i = 0; i < 2; i++) {
        int idx = tid + i * 128;
        int b = idx >> 2, g = idx & 3;
        *(float4*)&Xs[b][g * 4] = xwv[i];
    }
    __syncthreads();

    // ---- BN stats over batch for both hh-GEMM and ih (raw xw) columns ----
    {
        int c = tid & 15, q = tid >> 4;
        float sC = 0.f, s2C = 0.f, sX = 0.f, s2X = 0.f;
#pragma unroll
        for (int b = q * 8; b < q * 8 + 8; b++) {
            float v = Cs[b][c]; sC += v; s2C += v * v;
            float u = Xs[b][c]; sX += u; s2X += u * u;
        }
        redA[q][c] = sC; redB[q][c] = s2C; redC[q][c] = sX; redD[q][c] = s2X;
    }
    __syncthreads();
    if (tid < 16) {
        float sC = 0.f, s2C = 0.f, sX = 0.f, s2X = 0.f;
#pragma unroll
        for (int q = 0; q < 8; q++) {
            sC += redA[q][tid]; s2C += redB[q][tid];
            sX += redC[q][tid]; s2X += redD[q][tid];
        }
        int col = (tid >> 2) * HH + blk * 4 + (tid & 3);
        float muC = sC * (1.f / 64.f);
        float varC = fmaxf(s2C * (1.f / 64.f) - muC * muC, 0.f);
        float a = ghh[col] * rsqrtf(varC + EPSB);
        scH[tid] = a; shH[tid] = bthh[col] - muC * a;
        float muX = sX * (1.f / 64.f);
        float varX = fmaxf(s2X * (1.f / 64.f) - muX * muX, 0.f);
        float e = gih[col] * rsqrtf(varX + EPSB);
        scX[tid] = e; shX[tid] = btih[col] + bias[col] - muX * e;
    }
    __syncthreads();

    // ---- gates + cell update ----
#pragma unroll
    for (int i = 0; i < 2; i++) {
        int idx = tid + i * 128;
        int b = idx >> 2, j = idx & 3;
        float pre[4];
#pragma unroll
        for (int g = 0; g < 4; g++) {
            int c = g * 4 + j;
            pre[g] = Cs[b][c] * scH[c] + shH[c] + Xs[b][c] * scX[c] + shX[c];
        }
        float c1 = sigf(pre[0]) * coldr[i] + sigf(pre[1]) * tanh_f(pre[3]);
        c1s[b][j] = c1;
        oss[b][j] = sigf(pre[2]);
    }
    __syncthreads();

    // ---- BN stats over batch for the 4 cell columns ----
    if (tid < 32) {
        int j = tid & 3, q = tid >> 2;
        float s = 0.f, s2 = 0.f;
#pragma unroll
        for (int b = q * 8; b < q * 8 + 8; b++) { float v = c1s[b][j]; s += v; s2 += v * v; }
        redA[q][j] = s; redB[q][j] = s2;
    }
    __syncthreads();
    if (tid < 4) {
        float s = 0.f, s2 = 0.f;
#pragma unroll
        for (int q = 0; q < 8; q++) { s += redA[q][tid]; s2 += redB[q][tid]; }
        float mu = s * (1.f / 64.f);
        float var = fmaxf(s2 * (1.f / 64.f) - mu * mu, 0.f);
        int hcol = blk * 4 + tid;
        float a = gcb[hcol] * rsqrtf(var + EPSB);
        scc[tid] = a; shc[tid] = btcb[hcol] - mu * a;
    }
    __syncthreads();

    // ---- h update with length mask; write h, c, y ----
#pragma unroll
    for (int i = 0; i < 2; i++) {
        int idx = tid + i * 128;
        int b = idx >> 2, j = idx & 3;
        int hcol = blk * 4 + j;
        float c1 = c1s[b][j];
        float h1 = oss[b][j] * tanh_f(c1 * scc[j] + shc[j]);
        bool m = t < lenr[i];
        float hold = hin[b * HH + hcol];
        float hn = m ? h1 : hold;
        float cn = m ? c1 : coldr[i];
        hout[b * HH + hcol] = hn;
        g_c[b * HH + hcol] = cn;
        y_out[((size_t)t * BB + b) * HH + hcol] = hn;
    }
}

// ---------------- host orchestration ----------------
extern "C" void kernel_launch(void* const* d_in, const int* in_sizes, int n_in,
                              void* d_out, int out_size) {
    const float* x     = (const float*)d_in[0];
    const int* length  = (const int*)d_in[1];
    const float* w_ih0 = (const float*)d_in[2];
    const float* w_hh0 = (const float*)d_in[3];
    const float* b0    = (const float*)d_in[4];
    const float* gih0  = (const float*)d_in[5];
    const float* btih0 = (const float*)d_in[6];
    const float* ghh0  = (const float*)d_in[7];
    const float* bthh0 = (const float*)d_in[8];
    const float* gc0   = (const float*)d_in[9];
    const float* btc0  = (const float*)d_in[10];
    const float* w_ih1 = (const float*)d_in[11];
    const float* w_hh1 = (const float*)d_in[12];
    const float* b1    = (const float*)d_in[13];
    const float* gih1  = (const float*)d_in[14];
    const float* btih1 = (const float*)d_in[15];
    const float* ghh1  = (const float*)d_in[16];
    const float* bthh1 = (const float*)d_in[17];
    const float* gc1   = (const float*)d_in[18];
    const float* btc1  = (const float*)d_in[19];

    float* out = (float*)d_out;
    float* y1 = out;
    float* hn = out + (size_t)TT * BB * HH;
    float* cn = hn + 2 * BB * HH;

    float* p_y0 = nullptr;
    cudaGetSymbolAddress((void**)&p_y0, g_y0);

    const dim3 ggrid(GG / 64, (TT * BB) / 64);
    const int hcgrid = (BB * HH) / 256;

    // ---- layer 0 ----
    gemm_xw_kernel<<<ggrid, 256>>>(x, w_ih0, DD);
    pack_w_kernel<<<(HH * GG) / 256, 256>>>(w_hh0);
    init_hc_kernel<<<hcgrid, 256>>>();
    for (int t = 0; t < TT; t++)
        lstm_step_kernel<<<256, 128>>>(t, t & 1, ghh0, bthh0, gih0, btih0, b0,
                                       gc0, btc0, length, p_y0);
    copy_hc_kernel<<<hcgrid, 256>>>(hn, cn);

    // ---- layer 1 ----
    gemm_xw_kernel<<<ggrid, 256>>>(p_y0, w_ih1, HH);
    pack_w_kernel<<<(HH * GG) / 256, 256>>>(w_hh1);
    init_hc_kernel<<<hcgrid, 256>>>();
    for (int t = 0; t < TT; t++)
        lstm_step_kernel<<<256, 128>>>(t, t & 1, ghh1, bthh1, gih1, btih1, b1,
                                       gc1, btc1, length, y1);
    copy_hc_kernel<<<hcgrid, 256>>>(hn + BB * HH, cn + BB * HH);
}

// round 8
// speedup vs baseline: 1.4055x; 1.4055x over previous
#include <cuda_runtime.h>
#include <cstdint>
#include <cstddef>

#define TT 256
#define BB 64
#define DD 512
#define HH 1024
#define GG 4096
#define EPSB 1e-5f

// ---------------- scratch (device globals: no allocation allowed) ----------------
__device__ float g_xw[(size_t)TT * BB * GG];     // 256 MB: raw x@w_ih (BN applied in step)
__device__ float g_y0[(size_t)TT * BB * HH];     // 64 MB: layer-0 output
__device__ float g_h[2][BB * HH];                // ping-pong hidden state
__device__ float g_c[BB * HH];                   // cell state
__device__ float g_wdup[(size_t)HH * GG * 2];    // 128 MB: recurrent weights, packed + duplicated pairs

// ---------------- packed f32x2 + fast-math helpers ----------------
__device__ __forceinline__ void fma2(unsigned long long& d, unsigned long long a, unsigned long long b) {
    asm("fma.rn.f32x2 %0, %1, %2, %3;" : "=l"(d) : "l"(a), "l"(b), "l"(d));
}
__device__ __forceinline__ float2 upk2(unsigned long long v) {
    float lo, hi;
    asm("mov.b64 {%0, %1}, %2;" : "=f"(lo), "=f"(hi) : "l"(v));
    return make_float2(lo, hi);
}
__device__ __forceinline__ float tanh_f(float x) {
    float r;
    asm("tanh.approx.f32 %0, %1;" : "=f"(r) : "f"(x));
    return r;
}
__device__ __forceinline__ float sigf(float x) { return fmaf(tanh_f(0.5f * x), 0.5f, 0.5f); }

// ---------------- input GEMM: g_xw(raw) = A(16384 x K) @ W(K x 4096) ----------------
// 128x128 block tile, 256 threads, lane tile 8 rows x 8 cols (0.75 B LDS / MAC).
// Weights duplicated into smem pairs -> inner k: 2 LDS.128 (A) + 4 LDS.128 (W bcast) + 32 FFMA2.
__global__ __launch_bounds__(256) void gemm_xw_kernel(const float* __restrict__ A,
                                                      const float* __restrict__ W, int K) {
    __shared__ __align__(16) float As[2][8][132];   // [k][m] transposed
    __shared__ __align__(16) float Bd[2][8][260];   // [k][2*n] duplicated pairs
    const int n0 = blockIdx.x * 128, m0 = blockIdx.y * 128;
    const int tid = threadIdx.x;
    const int rg = tid & 15, cg = tid >> 4;
    const int r0 = rg * 8, c0 = cg * 8;
    const int ar = tid >> 1, ak = (tid & 1) * 4;    // A loader: row ar, k-quad ak
    const int bk = tid >> 5, bc = (tid & 31) * 4;   // B loader: k bk, 4 cols
    const float* pA = A + (size_t)(m0 + ar) * K + ak;
    const float* pB = W + (size_t)bk * GG + n0 + bc;

    unsigned long long acc[4][8] = {};   // 4 row-pairs x 8 cols

    float4 va = *(const float4*)pA;
    float4 vb = *(const float4*)pB;
    As[0][ak + 0][ar] = va.x; As[0][ak + 1][ar] = va.y;
    As[0][ak + 2][ar] = va.z; As[0][ak + 3][ar] = va.w;
    *(float2*)&Bd[0][bk][2 * (bc + 0)] = make_float2(vb.x, vb.x);
    *(float2*)&Bd[0][bk][2 * (bc + 1)] = make_float2(vb.y, vb.y);
    *(float2*)&Bd[0][bk][2 * (bc + 2)] = make_float2(vb.z, vb.z);
    *(float2*)&Bd[0][bk][2 * (bc + 3)] = make_float2(vb.w, vb.w);
    __syncthreads();

    int buf = 0;
    for (int kc = 8; kc <= K; kc += 8) {
        const bool more = (kc < K);
        if (more) {
            va = *(const float4*)(pA + kc);
            vb = *(const float4*)(pB + (size_t)kc * GG);
        }
#pragma unroll
        for (int k = 0; k < 8; k++) {
            ulonglong2 a0 = *(const ulonglong2*)&As[buf][k][r0];
            ulonglong2 a1 = *(const ulonglong2*)&As[buf][k][r0 + 4];
            ulonglong2 w01 = *(const ulonglong2*)&Bd[buf][k][2 * c0];
            ulonglong2 w23 = *(const ulonglong2*)&Bd[buf][k][2 * c0 + 4];
            ulonglong2 w45 = *(const ulonglong2*)&Bd[buf][k][2 * c0 + 8];
            ulonglong2 w67 = *(const ulonglong2*)&Bd[buf][k][2 * c0 + 12];
            unsigned long long avp[4] = {a0.x, a0.y, a1.x, a1.y};
            unsigned long long wr[8] = {w01.x, w01.y, w23.x, w23.y, w45.x, w45.y, w67.x, w67.y};
#pragma unroll
            for (int p = 0; p < 4; p++)
#pragma unroll
                for (int c = 0; c < 8; c++) fma2(acc[p][c], avp[p], wr[c]);
        }
        if (more) {
            int nb = buf ^ 1;
            As[nb][ak + 0][ar] = va.x; As[nb][ak + 1][ar] = va.y;
            As[nb][ak + 2][ar] = va.z; As[nb][ak + 3][ar] = va.w;
            *(float2*)&Bd[nb][bk][2 * (bc + 0)] = make_float2(vb.x, vb.x);
            *(float2*)&Bd[nb][bk][2 * (bc + 1)] = make_float2(vb.y, vb.y);
            *(float2*)&Bd[nb][bk][2 * (bc + 2)] = make_float2(vb.z, vb.z);
            *(float2*)&Bd[nb][bk][2 * (bc + 3)] = make_float2(vb.w, vb.w);
            __syncthreads();
            buf = nb;
        }
    }
#pragma unroll
    for (int p = 0; p < 4; p++) {
        float2 u[8];
#pragma unroll
        for (int c = 0; c < 8; c++) u[c] = upk2(acc[p][c]);
        float* o0 = &g_xw[(size_t)(m0 + r0 + 2 * p) * GG + n0 + c0];
        float* o1 = o0 + GG;
        *(float4*)o0       = make_float4(u[0].x, u[1].x, u[2].x, u[3].x);
        *(float4*)(o0 + 4) = make_float4(u[4].x, u[5].x, u[6].x, u[7].x);
        *(float4*)o1       = make_float4(u[0].y, u[1].y, u[2].y, u[3].y);
        *(float4*)(o1 + 4) = make_float4(u[4].y, u[5].y, u[6].y, u[7].y);
    }
}

// ---------------- pack w_hh: block blk owns 32 gate cols {g*H + blk*8 + j}, duplicated pairs ----------------
// g_wdup layout: [blk][k][2c + {0,1}]  (c in [0,32): gate = c>>3, j = c&7)
__global__ void pack_w_kernel(const float* __restrict__ w) {
    const int i = blockIdx.x * 256 + threadIdx.x;   // < HH*GG*2 = 2^23
    const int blk = i >> 16;
    const int k = (i >> 6) & (HH - 1);
    const int c = (i & 63) >> 1;
    g_wdup[i] = w[(size_t)k * GG + (c >> 3) * HH + blk * 8 + (c & 7)];
}

__global__ void init_hc_kernel() {
    const int i = blockIdx.x * 256 + threadIdx.x;
    if (i < BB * HH) { g_h[0][i] = 0.f; g_h[1][i] = 0.f; g_c[i] = 0.f; }
}

__global__ void copy_hc_kernel(float* __restrict__ oh, float* __restrict__ oc) {
    const int i = blockIdx.x * 256 + threadIdx.x;
    if (i < BB * HH) { oh[i] = g_h[0][i]; oc[i] = g_c[i]; }
}

// ---------------- one LSTM timestep ----------------
// 128 blocks x 256 threads. Block blk owns h-cols [blk*8, blk*8+8) and gate cols
// {g*1024 + blk*8 + j}. GEMM is K-split 4 ways: quarter q (2 warps) computes a full
// 64x32 partial over k in [256q, 256q+256) with lane tile 4 rows x 8 cols.
struct SG {   // GEMM staging
    float hsT[2][32][68];   // [k][b] transposed
    float wd[2][32][64];    // [k][2c] duplicated pairs
};
struct SR {   // post-GEMM reduction/epilogue
    float Cs[2][64][33];    // partial sums (q0+q2 -> [0], q1+q3 -> [1]); [0] later holds total
    float Xs[64][36];       // raw x@w_ih slice
    float redA[8][32], redB[8][32], redC[8][32], redD[8][32];
    float scH[32], shH[32], scX[32], shX[32];
    float c1s[64][9], oss[64][9];
    float scc[8], shc[8];
};

__global__ __launch_bounds__(256) void lstm_step_kernel(
    int t, int par,
    const float* __restrict__ ghh, const float* __restrict__ bthh,
    const float* __restrict__ gih, const float* __restrict__ btih,
    const float* __restrict__ bias,
    const float* __restrict__ gcb, const float* __restrict__ btcb,
    const int* __restrict__ length, float* __restrict__ y_out) {
    __shared__ __align__(16) union { SG g; SR r; } sm;

    const int blk = blockIdx.x, tid = threadIdx.x;
    const float* hin = g_h[par];
    float* hout = g_h[par ^ 1];
    const float* wp = g_wdup + (size_t)blk * 65536;

    // ---- epilogue prefetch (latency hidden under the GEMM) ----
    float4 xwv[2]; float coldr[2], holdr[2]; int lenr[2];
#pragma unroll
    for (int i = 0; i < 2; i++) {
        int f = tid * 2 + i;                       // 512 float4s of the 64x32 xw slice
        int b = f >> 3, sub = f & 7;
        int gate = sub >> 1, jj = (sub & 1) * 4;
        xwv[i] = *(const float4*)&g_xw[((size_t)t * BB + b) * GG + gate * HH + blk * 8 + jj];
        int bb = f >> 3, j = f & 7;                // gate-stage element mapping
        coldr[i] = g_c[bb * HH + blk * 8 + j];
        holdr[i] = hin[bb * HH + blk * 8 + j];
        lenr[i] = length[bb];
    }

    // ---- GEMM: 4 K-split partials of hin(64x1024) @ wp(1024x32) ----
    const int q = tid >> 6, tq = tid & 63;
    const int rg = tq & 15, cg = tq >> 4;
    const int r0 = rg * 4, c0 = cg * 8;
    unsigned long long acc[2][8] = {};

    float4 ph[2], pw[2];
#pragma unroll
    for (int i = 0; i < 2; i++) {
        int f = tid * 2 + i;
        ph[i] = *(const float4*)&hin[(f >> 3) * HH + (f & 7) * 4];
        pw[i] = *(const float4*)&wp[(tid * 2 + i) * 4];
    }
#pragma unroll
    for (int i = 0; i < 2; i++) {
        int f = tid * 2 + i;
        int b = f >> 3, kq = (f & 7) * 4;
        sm.g.hsT[0][kq + 0][b] = ph[i].x; sm.g.hsT[0][kq + 1][b] = ph[i].y;
        sm.g.hsT[0][kq + 2][b] = ph[i].z; sm.g.hsT[0][kq + 3][b] = ph[i].w;
        *(float4*)((float*)sm.g.wd[0] + (tid * 2 + i) * 4) = pw[i];
    }
    __syncthreads();

    int buf = 0;
    for (int kc = 32; kc <= HH; kc += 32) {
        const bool more = (kc < HH);
        if (more) {
#pragma unroll
            for (int i = 0; i < 2; i++) {
                int f = tid * 2 + i;
                ph[i] = *(const float4*)&hin[(f >> 3) * HH + kc + (f & 7) * 4];
                pw[i] = *(const float4*)&wp[(size_t)kc * 64 + (tid * 2 + i) * 4];
            }
        }
#pragma unroll
        for (int kk = 0; kk < 8; kk++) {
            int k = q * 8 + kk;
            ulonglong2 av  = *(const ulonglong2*)&sm.g.hsT[buf][k][r0];
            ulonglong2 w01 = *(const ulonglong2*)&sm.g.wd[buf][k][2 * c0];
            ulonglong2 w23 = *(const ulonglong2*)&sm.g.wd[buf][k][2 * c0 + 4];
            ulonglong2 w45 = *(const ulonglong2*)&sm.g.wd[buf][k][2 * c0 + 8];
            ulonglong2 w67 = *(const ulonglong2*)&sm.g.wd[buf][k][2 * c0 + 12];
            unsigned long long wr[8] = {w01.x, w01.y, w23.x, w23.y, w45.x, w45.y, w67.x, w67.y};
#pragma unroll
            for (int c = 0; c < 8; c++) {
                fma2(acc[0][c], av.x, wr[c]);
                fma2(acc[1][c], av.y, wr[c]);
            }
        }
        if (more) {
            int nb = buf ^ 1;
#pragma unroll
            for (int i = 0; i < 2; i++) {
                int f = tid * 2 + i;
                int b = f >> 3, kq = (f & 7) * 4;
                sm.g.hsT[nb][kq + 0][b] = ph[i].x; sm.g.hsT[nb][kq + 1][b] = ph[i].y;
                sm.g.hsT[nb][kq + 2][b] = ph[i].z; sm.g.hsT[nb][kq + 3][b] = ph[i].w;
                *(float4*)((float*)sm.g.wd[nb] + (tid * 2 + i) * 4) = pw[i];
            }
            __syncthreads();
            buf = nb;
        }
    }
    __syncthreads();   // GEMM reads done; smem is repurposed as SR below

    // ---- phase 1: quarters 0/1 store partials; everyone stores Xs ----
    if (q < 2) {
#pragma unroll
        for (int p = 0; p < 2; p++)
#pragma unroll
            for (int c = 0; c < 8; c++) {
                float2 u = upk2(acc[p][c]);
                sm.r.Cs[q][r0 + 2 * p][c0 + c]     = u.x;
                sm.r.Cs[q][r0 + 2 * p + 1][c0 + c] = u.y;
            }
    }
#pragma unroll
    for (int i = 0; i < 2; i++) {
        int f = tid * 2 + i;
        int b = f >> 3, sub = f & 7;
        int gate = sub >> 1, jj = (sub & 1) * 4;
        *(float4*)&sm.r.Xs[b][gate * 8 + jj] = xwv[i];
    }
    __syncthreads();

    // ---- phase 2: quarters 2/3 add their partials ----
    if (q >= 2) {
#pragma unroll
        for (int p = 0; p < 2; p++)
#pragma unroll
            for (int c = 0; c < 8; c++) {
                float2 u = upk2(acc[p][c]);
                sm.r.Cs[q - 2][r0 + 2 * p][c0 + c]     += u.x;
                sm.r.Cs[q - 2][r0 + 2 * p + 1][c0 + c] += u.y;
            }
    }
    __syncthreads();

    // ---- BN stats over batch for hh-GEMM and ih (raw xw) columns ----
    {
        int c = tid & 31, grp = tid >> 5;
        float sC = 0.f, s2C = 0.f, sX = 0.f, s2X = 0.f;
#pragma unroll
        for (int b = grp * 8; b < grp * 8 + 8; b++) {
            float v = sm.r.Cs[0][b][c] + sm.r.Cs[1][b][c];
            sm.r.Cs[0][b][c] = v;
            sC += v; s2C += v * v;
            float u = sm.r.Xs[b][c];
            sX += u; s2X += u * u;
        }
        sm.r.redA[grp][c] = sC; sm.r.redB[grp][c] = s2C;
        sm.r.redC[grp][c] = sX; sm.r.redD[grp][c] = s2X;
    }
    __syncthreads();
    if (tid < 32) {
        float sC = 0.f, s2C = 0.f, sX = 0.f, s2X = 0.f;
#pragma unroll
        for (int g = 0; g < 8; g++) {
            sC += sm.r.redA[g][tid]; s2C += sm.r.redB[g][tid];
            sX += sm.r.redC[g][tid]; s2X += sm.r.redD[g][tid];
        }
        int col = (tid >> 3) * HH + blk * 8 + (tid & 7);
        float muC = sC * (1.f / 64.f);
        float varC = fmaxf(s2C * (1.f / 64.f) - muC * muC, 0.f);
        float a = ghh[col] * rsqrtf(varC + EPSB);
        sm.r.scH[tid] = a; sm.r.shH[tid] = bthh[col] - muC * a;
        float muX = sX * (1.f / 64.f);
        float varX = fmaxf(s2X * (1.f / 64.f) - muX * muX, 0.f);
        float e = gih[col] * rsqrtf(varX + EPSB);
        sm.r.scX[tid] = e; sm.r.shX[tid] = btih[col] + bias[col] - muX * e;
    }
    __syncthreads();

    // ---- gates + cell update ----
#pragma unroll
    for (int i = 0; i < 2; i++) {
        int f = tid * 2 + i;
        int b = f >> 3, j = f & 7;
        float pre[4];
#pragma unroll
        for (int g = 0; g < 4; g++) {
            int c = g * 8 + j;
            pre[g] = sm.r.Cs[0][b][c] * sm.r.scH[c] + sm.r.shH[c]
                   + sm.r.Xs[b][c] * sm.r.scX[c] + sm.r.shX[c];
        }
        float c1 = sigf(pre[0]) * coldr[i] + sigf(pre[1]) * tanh_f(pre[3]);
        sm.r.c1s[b][j] = c1;
        sm.r.oss[b][j] = sigf(pre[2]);
    }
    __syncthreads();

    // ---- BN stats over batch for the 8 cell columns ----
    if (tid < 64) {
        int j = tid & 7, grp = tid >> 3;
        float s = 0.f, s2 = 0.f;
#pragma unroll
        for (int b = grp * 8; b < grp * 8 + 8; b++) {
            float v = sm.r.c1s[b][j]; s += v; s2 += v * v;
        }
        sm.r.redA[grp][j] = s; sm.r.redB[grp][j] = s2;
    }
    __syncthreads();
    if (tid < 8) {
        float s = 0.f, s2 = 0.f;
#pragma unroll
        for (int g = 0; g < 8; g++) { s += sm.r.redA[g][tid]; s2 += sm.r.redB[g][tid]; }
        float mu = s * (1.f / 64.f);
        float var = fmaxf(s2 * (1.f / 64.f) - mu * mu, 0.f);
        int hcol = blk * 8 + tid;
        float a = gcb[hcol] * rsqrtf(var + EPSB);
        sm.r.scc[tid] = a; sm.r.shc[tid] = btcb[hcol] - mu * a;
    }
    __syncthreads();

    // ---- h update with length mask; write h, c, y ----
#pragma unroll
    for (int i = 0; i < 2; i++) {
        int f = tid * 2 + i;
        int b = f >> 3, j = f & 7;
        int hcol = blk * 8 + j;
        float c1 = sm.r.c1s[b][j];
        float h1 = sm.r.oss[b][j] * tanh_f(c1 * sm.r.scc[j] + sm.r.shc[j]);
        bool m = t < lenr[i];
        float hn = m ? h1 : holdr[i];
        float cn = m ? c1 : coldr[i];
        hout[b * HH + hcol] = hn;
        g_c[b * HH + hcol] = cn;
        y_out[((size_t)t * BB + b) * HH + hcol] = hn;
    }
}

// ---------------- host orchestration ----------------
extern "C" void kernel_launch(void* const* d_in, const int* in_sizes, int n_in,
                              void* d_out, int out_size) {
    const float* x     = (const float*)d_in[0];
    const int* length  = (const int*)d_in[1];
    const float* w_ih0 = (const float*)d_in[2];
    const float* w_hh0 = (const float*)d_in[3];
    const float* b0    = (const float*)d_in[4];
    const float* gih0  = (const float*)d_in[5];
    const float* btih0 = (const float*)d_in[6];
    const float* ghh0  = (const float*)d_in[7];
    const float* bthh0 = (const float*)d_in[8];
    const float* gc0   = (const float*)d_in[9];
    const float* btc0  = (const float*)d_in[10];
    const float* w_ih1 = (const float*)d_in[11];
    const float* w_hh1 = (const float*)d_in[12];
    const float* b1    = (const float*)d_in[13];
    const float* gih1  = (const float*)d_in[14];
    const float* btih1 = (const float*)d_in[15];
    const float* ghh1  = (const float*)d_in[16];
    const float* bthh1 = (const float*)d_in[17];
    const float* gc1   = (const float*)d_in[18];
    const float* btc1  = (const float*)d_in[19];

    float* out = (float*)d_out;
    float* y1 = out;
    float* hn = out + (size_t)TT * BB * HH;
    float* cn = hn + 2 * BB * HH;

    float* p_y0 = nullptr;
    cudaGetSymbolAddress((void**)&p_y0, g_y0);

    const dim3 ggrid(GG / 128, (TT * BB) / 128);
    const int hcgrid = (BB * HH) / 256;
    const int packgrid = (HH * GG * 2) / 256;

    // ---- layer 0 ----
    gemm_xw_kernel<<<ggrid, 256>>>(x, w_ih0, DD);
    pack_w_kernel<<<packgrid, 256>>>(w_hh0);
    init_hc_kernel<<<hcgrid, 256>>>();
    for (int t = 0; t < TT; t++)
        lstm_step_kernel<<<128, 256>>>(t, t & 1, ghh0, bthh0, gih0, btih0, b0,
                                       gc0, btc0, length, p_y0);
    copy_hc_kernel<<<hcgrid, 256>>>(hn, cn);

    // ---- layer 1 ----
    gemm_xw_kernel<<<ggrid, 256>>>(p_y0, w_ih1, HH);
    pack_w_kernel<<<packgrid, 256>>>(w_hh1);
    init_hc_kernel<<<hcgrid, 256>>>();
    for (int t = 0; t < TT; t++)
        lstm_step_kernel<<<128, 256>>>(t, t & 1, ghh1, bthh1, gih1, btih1, b1,
                                       gc1, btc1, length, y1);
    copy_hc_kernel<<<hcgrid, 256>>>(hn + BB * HH, cn + BB * HH);
}